// round 8
// baseline (speedup 1.0000x reference)
#include <cuda_runtime.h>
#include <math.h>

#define NV 1024
#define NB 16
#define GRID_DIM 16                 // 16x16 cells of 25m over [0,400)
#define NCELL (GRID_DIM * GRID_DIM)
#define EPB 16                      // egos per block
#define SLOTS 8
#define MTHREADS (EPB * SLOTS)      // 128

// Original-order data
__device__ float2 g_pos[NB * NV];         // {x, y}
__device__ float4 g_att[NB * NV];         // {cos, sin, v, 0}
// Cell-sorted per-batch data (stop-check only; read via L2 in main kernel)
__device__ float2 g_spos[NB * NV];
__device__ float4 g_satt[NB * NV];
__device__ int    g_cstart[NB * (NCELL + 1)];

// Wide kernel: per-vehicle sincos + SoA write.
__global__ __launch_bounds__(256) void sincos_kernel(const float* __restrict__ state)
{
    int idx = blockIdx.x * 256 + threadIdx.x;       // idx = bat*NV + i
    if (idx >= NB * NV) return;
    const float* p = state + (size_t)idx * 5;
    float x = p[0], y = p[1], v = p[2], psi = p[3];
    float sp, cp;
    sincosf(psi, &sp, &cp);
    g_pos[idx] = make_float2(x, y);
    g_att[idx] = make_float4(cp, sp, v, 0.0f);
}

// One block per batch: counting-sort into the 16x16 grid (no sincos).
__global__ __launch_bounds__(256) void sort_kernel()
{
    __shared__ int counts[NCELL];
    __shared__ int scan[NCELL];
    __shared__ int offs[NCELL];

    const int bat = blockIdx.x;
    const int t = threadIdx.x;
    const int base = bat * NV;

    counts[t] = 0;
    __syncthreads();

    float2 pos[4];
    int cl[4];
    #pragma unroll
    for (int q = 0; q < 4; q++) {
        int i = t + q * 256;
        pos[q] = g_pos[base + i];
        int cx = max(0, min(GRID_DIM - 1, (int)(pos[q].x * 0.04f)));
        int cy = max(0, min(GRID_DIM - 1, (int)(pos[q].y * 0.04f)));
        cl[q] = cy * GRID_DIM + cx;
        atomicAdd(&counts[cl[q]], 1);
    }
    __syncthreads();

    scan[t] = counts[t];
    __syncthreads();
    for (int d = 1; d < NCELL; d <<= 1) {
        int val = (t >= d) ? scan[t - d] : 0;
        __syncthreads();
        scan[t] += val;
        __syncthreads();
    }
    {
        int e = scan[t] - counts[t];               // exclusive
        offs[t] = e;
        g_cstart[bat * (NCELL + 1) + t] = e;
    }
    if (t == 0) g_cstart[bat * (NCELL + 1) + NCELL] = NV;
    __syncthreads();

    #pragma unroll
    for (int q = 0; q < 4; q++) {
        int i = t + q * 256;
        int p = atomicAdd(&offs[cl[q]], 1);
        g_spos[base + p] = pos[q];
        g_satt[base + p] = g_att[base + i];
    }
}

__global__ __launch_bounds__(MTHREADS)
void rulepolicy_kernel(const float* __restrict__ lengths,
                       const float* __restrict__ v0p,
                       const float* __restrict__ s0p,
                       const float* __restrict__ dthp,
                       const float* __restrict__ amaxp,
                       const float* __restrict__ bp,
                       float* __restrict__ out)
{
    __shared__ float4 poso[NV / 2];        // original order, 2 vehicles per float4 (8 KB)
    __shared__ int    cstart[NCELL + 1];

    const int bat = blockIdx.y;
    const int t = threadIdx.x;
    const int base = bat * NV;

    for (int i = t; i < NV / 2; i += MTHREADS)
        poso[i] = ((const float4*)g_pos)[base / 2 + i];
    for (int i = t; i < NCELL + 1; i += MTHREADS)
        cstart[i] = g_cstart[bat * (NCELL + 1) + i];
    __syncthreads();

    const int slot = t & (SLOTS - 1);
    const int jl   = blockIdx.x * EPB + (t >> 3);

    const float4 att = g_att[base + jl];
    const float cj = att.x, sj = att.y, vj = att.z;
    const float2 ep = g_pos[base + jl];
    const float xj = ep.x, yj = ep.y;

    const float C20SQ = 0.8830222215594891f;   // cos^2(20deg)
    const float C45   = 0.7071067811865476f;   // cos(45deg)
    const float INF   = __int_as_float(0x7f800000);

    // ── Leader scan, 4 independent accumulator chains ──
    float bA = INF, bB = INF, bC = INF, bD = INF;
    int   iA = 0,   iB = 0,   iC = 0,   iD = 0;

    #pragma unroll 8
    for (int k = slot; k < NV / 2; k += 2 * SLOTS) {
        float4 p = poso[k];
        float4 q = poso[k + SLOTS];

        float dxa = p.x - xj, dya = p.y - yj;
        float r2a = fmaf(dxa, dxa, dya * dya);
        float nda = fmaf(dxa, cj, dya * sj);
        float ma  = fminf(nda, fmaf(-C20SQ, r2a, nda * nda));
        float ea  = (ma > 0.0f) ? nda : INF;
        bool  ca  = ea < bA;
        bA = ca ? ea : bA;  iA = ca ? 2 * k : iA;

        float dxb = p.z - xj, dyb = p.w - yj;
        float r2b = fmaf(dxb, dxb, dyb * dyb);
        float ndb = fmaf(dxb, cj, dyb * sj);
        float mb  = fminf(ndb, fmaf(-C20SQ, r2b, ndb * ndb));
        float eb  = (mb > 0.0f) ? ndb : INF;
        bool  cb  = eb < bB;
        bB = cb ? eb : bB;  iB = cb ? 2 * k + 1 : iB;

        float dxc = q.x - xj, dyc = q.y - yj;
        float r2c = fmaf(dxc, dxc, dyc * dyc);
        float ndc = fmaf(dxc, cj, dyc * sj);
        float mc  = fminf(ndc, fmaf(-C20SQ, r2c, ndc * ndc));
        float ec  = (mc > 0.0f) ? ndc : INF;
        bool  cc  = ec < bC;
        bC = cc ? ec : bC;  iC = cc ? 2 * (k + SLOTS) : iC;

        float dxd = q.z - xj, dyd = q.w - yj;
        float r2d = fmaf(dxd, dxd, dyd * dyd);
        float ndd = fmaf(dxd, cj, dyd * sj);
        float md  = fminf(ndd, fmaf(-C20SQ, r2d, ndd * ndd));
        float ed  = (md > 0.0f) ? ndd : INF;
        bool  cd  = ed < bD;
        bD = cd ? ed : bD;  iD = cd ? 2 * (k + SLOTS) + 1 : iD;
    }

    // Merge 4 chains (tie -> smaller original index).
    float best = bA; int bidx = iA;
    if (bB < best || (bB == best && iB < bidx)) { best = bB; bidx = iB; }
    if (bC < best || (bC == best && iC < bidx)) { best = bC; bidx = iC; }
    if (bD < best || (bD == best && iD < bidx)) { best = bD; bidx = iD; }

    // ── Stop check: 3x3 cell neighborhood via L2 (~36 candidates) ──
    int stopi = 0;
    {
        int cx = max(0, min(GRID_DIM - 1, (int)(xj * 0.04f)));
        int cy = max(0, min(GRID_DIM - 1, (int)(yj * 0.04f)));
        int x0 = max(cx - 1, 0), x1 = min(cx + 1, GRID_DIM - 1);
        int y0 = max(cy - 1, 0), y1 = min(cy + 1, GRID_DIM - 1);
        for (int ry = y0; ry <= y1; ry++) {
            int beg = cstart[ry * GRID_DIM + x0];
            int end = cstart[ry * GRID_DIM + x1 + 1];
            for (int i = beg + slot; i < end; i += SLOTS) {
                float2 p = __ldg(&g_spos[base + i]);
                float4 a = __ldg(&g_satt[base + i]);
                float dx = p.x - xj, dy = p.y - yj;
                float r2 = fmaf(dx, dx, dy * dy);
                float nd = fmaf(dx, cj, dy * sj);
                float cpd = fmaf(a.x, cj, a.y * sj);  // cos(psi_i - psi_j)
                // dr<20 & |delpsi|<60 (nd>0 & nd^2>r2/4) & |dpsi|>45 & v_i>v_j
                stopi |= (int)((r2 < 400.0f) & (nd > 0.0f)
                               & (nd * nd > 0.25f * r2)
                               & (cpd < C45) & (a.z > vj));
            }
        }
    }

    // ── Reduce across the 8 slots of this ego (consecutive lanes) ──
    #pragma unroll
    for (int m = 1; m <= 4; m <<= 1) {
        float ob = __shfl_xor_sync(0xFFFFFFFFu, best, m);
        int   oi = __shfl_xor_sync(0xFFFFFFFFu, bidx, m);
        int   os = __shfl_xor_sync(0xFFFFFFFFu, stopi, m);
        if (ob < best || (ob == best && oi < bidx)) { best = ob; bidx = oi; }
        stopi |= os;
    }

    if (slot == 0) {
        const float V0 = v0p[0], S0 = s0p[0], DTH = dthp[0];
        const float AMAX = amaxp[0], BB = bp[0];

        float4 ld = g_att[base + bidx];         // {cos, sin, v} of leader (orig index)
        float dvx = ld.z * ld.x - vj * cj;
        float dvy = ld.z * ld.y - vj * sj;
        float ndv = fmaf(dvx, cj, dvy * sj);    // dv*cos(vdelpsi), exact incl. dv=0

        float sal   = best - lengths[jl];
        float sstar = S0 + vj * DTH + (vj * ndv) / (2.0f * sqrtf(AMAX * BB));
        float q  = vj / V0;
        float q2 = q * q;
        float afree = AMAX * (1.0f - q2 * q2);

        float action;
        if (stopi) {
            action = afree - AMAX;              // ratio = 1
        } else if (isinf(sal) || isnan(sal)) {
            action = afree;
        } else {
            float r = sstar / sal;
            action = afree - AMAX * r * r;
        }
        out[bat * NV + jl] = action;
    }
}

extern "C" void kernel_launch(void* const* d_in, const int* in_sizes, int n_in,
                              void* d_out, int out_size)
{
    const float* state   = (const float*)d_in[0];
    const float* lengths = (const float*)d_in[1];
    const float* v0      = (const float*)d_in[2];
    const float* s0      = (const float*)d_in[3];
    const float* dth     = (const float*)d_in[4];
    const float* amax    = (const float*)d_in[5];
    const float* b       = (const float*)d_in[6];
    float* out = (float*)d_out;

    sincos_kernel<<<NB * NV / 256, 256>>>(state);
    sort_kernel<<<NB, 256>>>();
    dim3 grid(NV / EPB, NB);
    rulepolicy_kernel<<<grid, MTHREADS>>>(lengths, v0, s0, dth, amax, b, out);
}

// round 9
// speedup vs baseline: 1.0504x; 1.0504x over previous
#include <cuda_runtime.h>
#include <math.h>

#define NV 1024
#define NB 16
#define GRID_DIM 16                 // 16x16 cells of 25m over [0,400)
#define NCELL (GRID_DIM * GRID_DIM)
#define EPB 16                      // egos per block
#define SLOTS 8
#define MTHREADS (EPB * SLOTS)      // 128

// Original-order data
__device__ float2 g_pos[NB * NV];         // {x, y}
__device__ float4 g_att[NB * NV];         // {cos, sin, v, 0}
// Cell-sorted per-batch data (stop-check only; read via L2 in main kernel)
__device__ float2 g_spos[NB * NV];
__device__ float4 g_satt[NB * NV];
__device__ int    g_cstart[NB * (NCELL + 1)];

// One block per batch: sincos + counting-sort into the 16x16 grid. Single
// prep launch — at this problem scale every extra kernel launch costs ~3-4us.
__global__ __launch_bounds__(512) void prep_kernel(const float* __restrict__ state)
{
    __shared__ int counts[NCELL];
    __shared__ int scan[NCELL];
    __shared__ int offs[NCELL];

    const int bat = blockIdx.x;
    const int t = threadIdx.x;
    const int base = bat * NV;
    const float* st = state + (size_t)bat * NV * 5;

    if (t < NCELL) counts[t] = 0;
    __syncthreads();

    float x[2], y[2], v[2], c[2], s[2];
    int cl[2];
    #pragma unroll
    for (int q = 0; q < 2; q++) {
        int i = t + q * 512;
        const float* p = st + i * 5;
        x[q] = p[0]; y[q] = p[1]; v[q] = p[2];
        float psi = p[3];
        sincosf(psi, &s[q], &c[q]);
        int cx = max(0, min(GRID_DIM - 1, (int)(x[q] * 0.04f)));
        int cy = max(0, min(GRID_DIM - 1, (int)(y[q] * 0.04f)));
        cl[q] = cy * GRID_DIM + cx;
        atomicAdd(&counts[cl[q]], 1);
        g_pos[base + i] = make_float2(x[q], y[q]);
        g_att[base + i] = make_float4(c[q], s[q], v[q], 0.0f);
    }
    __syncthreads();

    if (t < NCELL) scan[t] = counts[t];
    __syncthreads();
    for (int d = 1; d < NCELL; d <<= 1) {
        int val = 0;
        if (t < NCELL && t >= d) val = scan[t - d];
        __syncthreads();
        if (t < NCELL) scan[t] += val;
        __syncthreads();
    }
    if (t < NCELL) {
        int e = scan[t] - counts[t];               // exclusive
        offs[t] = e;
        g_cstart[bat * (NCELL + 1) + t] = e;
    }
    if (t == 0) g_cstart[bat * (NCELL + 1) + NCELL] = NV;
    __syncthreads();

    #pragma unroll
    for (int q = 0; q < 2; q++) {
        int p = atomicAdd(&offs[cl[q]], 1);
        g_spos[base + p] = make_float2(x[q], y[q]);
        g_satt[base + p] = make_float4(c[q], s[q], v[q], 0.0f);
    }
}

__global__ __launch_bounds__(MTHREADS)
void rulepolicy_kernel(const float* __restrict__ lengths,
                       const float* __restrict__ v0p,
                       const float* __restrict__ s0p,
                       const float* __restrict__ dthp,
                       const float* __restrict__ amaxp,
                       const float* __restrict__ bp,
                       float* __restrict__ out)
{
    __shared__ float4 poso[NV / 2];        // original order, 2 vehicles per float4 (8 KB)
    __shared__ int    cstart[NCELL + 1];

    const int bat = blockIdx.y;
    const int t = threadIdx.x;
    const int base = bat * NV;

    for (int i = t; i < NV / 2; i += MTHREADS)
        poso[i] = ((const float4*)g_pos)[base / 2 + i];
    for (int i = t; i < NCELL + 1; i += MTHREADS)
        cstart[i] = g_cstart[bat * (NCELL + 1) + i];
    __syncthreads();

    const int slot = t & (SLOTS - 1);
    const int jl   = blockIdx.x * EPB + (t >> 3);

    const float4 att = g_att[base + jl];
    const float cj = att.x, sj = att.y, vj = att.z;
    const float2 ep = g_pos[base + jl];
    const float xj = ep.x, yj = ep.y;

    const float C20SQ = 0.8830222215594891f;   // cos^2(20deg)
    const float C45   = 0.7071067811865476f;   // cos(45deg)
    const float INF   = __int_as_float(0x7f800000);

    // ── Leader scan, 4 independent accumulator chains ──
    float bA = INF, bB = INF, bC = INF, bD = INF;
    int   iA = 0,   iB = 0,   iC = 0,   iD = 0;

    #pragma unroll 8
    for (int k = slot; k < NV / 2; k += 2 * SLOTS) {
        float4 p = poso[k];
        float4 q = poso[k + SLOTS];

        float dxa = p.x - xj, dya = p.y - yj;
        float r2a = fmaf(dxa, dxa, dya * dya);
        float nda = fmaf(dxa, cj, dya * sj);
        float ma  = fminf(nda, fmaf(-C20SQ, r2a, nda * nda));
        float ea  = (ma > 0.0f) ? nda : INF;
        bool  ca  = ea < bA;
        bA = ca ? ea : bA;  iA = ca ? 2 * k : iA;

        float dxb = p.z - xj, dyb = p.w - yj;
        float r2b = fmaf(dxb, dxb, dyb * dyb);
        float ndb = fmaf(dxb, cj, dyb * sj);
        float mb  = fminf(ndb, fmaf(-C20SQ, r2b, ndb * ndb));
        float eb  = (mb > 0.0f) ? ndb : INF;
        bool  cb  = eb < bB;
        bB = cb ? eb : bB;  iB = cb ? 2 * k + 1 : iB;

        float dxc = q.x - xj, dyc = q.y - yj;
        float r2c = fmaf(dxc, dxc, dyc * dyc);
        float ndc = fmaf(dxc, cj, dyc * sj);
        float mc  = fminf(ndc, fmaf(-C20SQ, r2c, ndc * ndc));
        float ec  = (mc > 0.0f) ? ndc : INF;
        bool  cc  = ec < bC;
        bC = cc ? ec : bC;  iC = cc ? 2 * (k + SLOTS) : iC;

        float dxd = q.z - xj, dyd = q.w - yj;
        float r2d = fmaf(dxd, dxd, dyd * dyd);
        float ndd = fmaf(dxd, cj, dyd * sj);
        float md  = fminf(ndd, fmaf(-C20SQ, r2d, ndd * ndd));
        float ed  = (md > 0.0f) ? ndd : INF;
        bool  cd  = ed < bD;
        bD = cd ? ed : bD;  iD = cd ? 2 * (k + SLOTS) + 1 : iD;
    }

    // Merge 4 chains (tie -> smaller original index).
    float best = bA; int bidx = iA;
    if (bB < best || (bB == best && iB < bidx)) { best = bB; bidx = iB; }
    if (bC < best || (bC == best && iC < bidx)) { best = bC; bidx = iC; }
    if (bD < best || (bD == best && iD < bidx)) { best = bD; bidx = iD; }

    // ── Stop check: 3x3 cell neighborhood via L2 (~36 candidates) ──
    int stopi = 0;
    {
        int cx = max(0, min(GRID_DIM - 1, (int)(xj * 0.04f)));
        int cy = max(0, min(GRID_DIM - 1, (int)(yj * 0.04f)));
        int x0 = max(cx - 1, 0), x1 = min(cx + 1, GRID_DIM - 1);
        int y0 = max(cy - 1, 0), y1 = min(cy + 1, GRID_DIM - 1);
        for (int ry = y0; ry <= y1; ry++) {
            int beg = cstart[ry * GRID_DIM + x0];
            int end = cstart[ry * GRID_DIM + x1 + 1];
            for (int i = beg + slot; i < end; i += SLOTS) {
                float2 p = __ldg(&g_spos[base + i]);
                float4 a = __ldg(&g_satt[base + i]);
                float dx = p.x - xj, dy = p.y - yj;
                float r2 = fmaf(dx, dx, dy * dy);
                float nd = fmaf(dx, cj, dy * sj);
                float cpd = fmaf(a.x, cj, a.y * sj);  // cos(psi_i - psi_j)
                // dr<20 & |delpsi|<60 (nd>0 & nd^2>r2/4) & |dpsi|>45 & v_i>v_j
                stopi |= (int)((r2 < 400.0f) & (nd > 0.0f)
                               & (nd * nd > 0.25f * r2)
                               & (cpd < C45) & (a.z > vj));
            }
        }
    }

    // ── Reduce across the 8 slots of this ego (consecutive lanes) ──
    #pragma unroll
    for (int m = 1; m <= 4; m <<= 1) {
        float ob = __shfl_xor_sync(0xFFFFFFFFu, best, m);
        int   oi = __shfl_xor_sync(0xFFFFFFFFu, bidx, m);
        int   os = __shfl_xor_sync(0xFFFFFFFFu, stopi, m);
        if (ob < best || (ob == best && oi < bidx)) { best = ob; bidx = oi; }
        stopi |= os;
    }

    if (slot == 0) {
        const float V0 = v0p[0], S0 = s0p[0], DTH = dthp[0];
        const float AMAX = amaxp[0], BB = bp[0];

        float4 ld = g_att[base + bidx];         // {cos, sin, v} of leader (orig index)
        float dvx = ld.z * ld.x - vj * cj;
        float dvy = ld.z * ld.y - vj * sj;
        float ndv = fmaf(dvx, cj, dvy * sj);    // dv*cos(vdelpsi), exact incl. dv=0

        float sal   = best - lengths[jl];
        float sstar = S0 + vj * DTH + (vj * ndv) / (2.0f * sqrtf(AMAX * BB));
        float q  = vj / V0;
        float q2 = q * q;
        float afree = AMAX * (1.0f - q2 * q2);

        float action;
        if (stopi) {
            action = afree - AMAX;              // ratio = 1
        } else if (isinf(sal) || isnan(sal)) {
            action = afree;
        } else {
            float r = sstar / sal;
            action = afree - AMAX * r * r;
        }
        out[bat * NV + jl] = action;
    }
}

extern "C" void kernel_launch(void* const* d_in, const int* in_sizes, int n_in,
                              void* d_out, int out_size)
{
    const float* state   = (const float*)d_in[0];
    const float* lengths = (const float*)d_in[1];
    const float* v0      = (const float*)d_in[2];
    const float* s0      = (const float*)d_in[3];
    const float* dth     = (const float*)d_in[4];
    const float* amax    = (const float*)d_in[5];
    const float* b       = (const float*)d_in[6];
    float* out = (float*)d_out;

    prep_kernel<<<NB, 512>>>(state);
    dim3 grid(NV / EPB, NB);
    rulepolicy_kernel<<<grid, MTHREADS>>>(lengths, v0, s0, dth, amax, b, out);
}

// round 10
// speedup vs baseline: 1.1456x; 1.0906x over previous
#include <cuda_runtime.h>
#include <math.h>

#define NV 1024
#define NB 16
#define GRID_DIM 16                 // 16x16 cells of 25m over [0,400)
#define NCELL (GRID_DIM * GRID_DIM)
#define WPB 16                      // warps (=egos) per block
#define BTHREADS (WPB * 32)         // 512

// Original-order data
__device__ float2 g_pos[NB * NV];         // {x, y}
__device__ float4 g_att[NB * NV];         // {cos, sin, v, 0}
// Cell-sorted per-batch data
__device__ float2 g_spos[NB * NV];
__device__ float4 g_satt[NB * NV];
__device__ int    g_cstart[NB * (NCELL + 1)];

// One block per batch: sincos + counting-sort into the 16x16 grid.
__global__ __launch_bounds__(512) void prep_kernel(const float* __restrict__ state)
{
    __shared__ int counts[NCELL];
    __shared__ int scan[NCELL];
    __shared__ int offs[NCELL];

    const int bat = blockIdx.x;
    const int t = threadIdx.x;
    const int base = bat * NV;
    const float* st = state + (size_t)bat * NV * 5;

    if (t < NCELL) counts[t] = 0;
    __syncthreads();

    float x[2], y[2], v[2], c[2], s[2];
    int cl[2];
    #pragma unroll
    for (int q = 0; q < 2; q++) {
        int i = t + q * 512;
        const float* p = st + i * 5;
        x[q] = p[0]; y[q] = p[1]; v[q] = p[2];
        float psi = p[3];
        sincosf(psi, &s[q], &c[q]);
        int cx = max(0, min(GRID_DIM - 1, (int)(x[q] * 0.04f)));
        int cy = max(0, min(GRID_DIM - 1, (int)(y[q] * 0.04f)));
        cl[q] = cy * GRID_DIM + cx;
        atomicAdd(&counts[cl[q]], 1);
        g_pos[base + i] = make_float2(x[q], y[q]);
        g_att[base + i] = make_float4(c[q], s[q], v[q], 0.0f);
    }
    __syncthreads();

    if (t < NCELL) scan[t] = counts[t];
    __syncthreads();
    for (int d = 1; d < NCELL; d <<= 1) {
        int val = 0;
        if (t < NCELL && t >= d) val = scan[t - d];
        __syncthreads();
        if (t < NCELL) scan[t] += val;
        __syncthreads();
    }
    if (t < NCELL) {
        int e = scan[t] - counts[t];               // exclusive
        offs[t] = e;
        g_cstart[bat * (NCELL + 1) + t] = e;
    }
    if (t == 0) g_cstart[bat * (NCELL + 1) + NCELL] = NV;
    __syncthreads();

    #pragma unroll
    for (int q = 0; q < 2; q++) {
        int p = atomicAdd(&offs[cl[q]], 1);
        g_spos[base + p] = make_float2(x[q], y[q]);
        g_satt[base + p] = make_float4(c[q], s[q], v[q], 0.0f);
    }
}

// One warp per ego. 5x5-cell neighborhood scan covers the stop check (needs
// dr<20 => within 3x3) and, with probability ~0.99, the leader too: any
// candidate outside the 5x5 has dr>=50 so nd >= 50*cos20 = 46.98. Fallback:
// full scan (rare, warp-uniform).
__global__ __launch_bounds__(BTHREADS)
void rulepolicy_kernel(const float* __restrict__ lengths,
                       const float* __restrict__ v0p,
                       const float* __restrict__ s0p,
                       const float* __restrict__ dthp,
                       const float* __restrict__ amaxp,
                       const float* __restrict__ bp,
                       float* __restrict__ out)
{
    __shared__ float2 spos[NV];            // 8 KB, cell-sorted
    __shared__ float4 satt[NV];            // 16 KB
    __shared__ int    cstart[NCELL + 1];

    const int bat = blockIdx.y;
    const int t = threadIdx.x;
    const int base = bat * NV;

    for (int i = t; i < NV / 2; i += BTHREADS)
        ((float4*)spos)[i] = ((const float4*)g_spos)[base / 2 + i];
    for (int i = t; i < NV; i += BTHREADS)
        satt[i] = g_satt[base + i];
    for (int i = t; i < NCELL + 1; i += BTHREADS)
        cstart[i] = g_cstart[bat * (NCELL + 1) + i];
    __syncthreads();

    const int lane = t & 31;
    const int w = t >> 5;
    const int jl = blockIdx.x * WPB + w;           // ego original index

    const float4 att = g_att[base + jl];
    const float cj = att.x, sj = att.y, vj = att.z;
    const float2 ep = g_pos[base + jl];
    const float xj = ep.x, yj = ep.y;

    const float C20SQ = 0.8830222215594891f;   // cos^2(20deg)
    const float C45   = 0.7071067811865476f;   // cos(45deg)
    const float INF   = __int_as_float(0x7f800000);
    const float TERM  = 46.9f;                 // < 50*cos20 = 46.984 (safe margin)

    float best = INF;
    int   bidx = 0;
    int   stopi = 0;

    // ── 5x5 neighborhood: leader + stop in one pass ──
    {
        int cx = max(0, min(GRID_DIM - 1, (int)(xj * 0.04f)));
        int cy = max(0, min(GRID_DIM - 1, (int)(yj * 0.04f)));
        int x0 = max(cx - 2, 0), x1 = min(cx + 2, GRID_DIM - 1);
        int y0 = max(cy - 2, 0), y1 = min(cy + 2, GRID_DIM - 1);
        for (int ry = y0; ry <= y1; ry++) {
            int beg = cstart[ry * GRID_DIM + x0];
            int end = cstart[ry * GRID_DIM + x1 + 1];
            for (int i = beg + lane; i < end; i += 32) {
                float2 p = spos[i];
                float4 a = satt[i];
                float dx = p.x - xj, dy = p.y - yj;
                float r2 = fmaf(dx, dx, dy * dy);
                float nd = fmaf(dx, cj, dy * sj);          // dr*cos(delpsi)
                float m  = fminf(nd, fmaf(-C20SQ, r2, nd * nd));
                float e  = (m > 0.0f) ? nd : INF;
                bool  c  = e < best;
                best = c ? e : best;  bidx = c ? i : bidx;
                float cpd = fmaf(a.x, cj, a.y * sj);       // cos(psi_i-psi_j)
                stopi |= (int)((r2 < 400.0f) & (nd > 0.0f)
                               & (nd * nd > 0.25f * r2)
                               & (cpd < C45) & (a.z > vj));
            }
        }
    }

    // ── Warp reduce (min + index tiebreak + OR); result uniform across lanes ──
    #pragma unroll
    for (int m = 1; m <= 16; m <<= 1) {
        float ob = __shfl_xor_sync(0xFFFFFFFFu, best, m);
        int   oi = __shfl_xor_sync(0xFFFFFFFFu, bidx, m);
        int   os = __shfl_xor_sync(0xFFFFFFFFu, stopi, m);
        if (ob < best || (ob == best && oi < bidx)) { best = ob; bidx = oi; }
        stopi |= os;
    }

    // ── Rare fallback: neighborhood couldn't certify the leader ──
    if (best >= TERM) {
        // lane-local rescans start from the (uniform) neighborhood result
        for (int i = lane; i < NV; i += 32) {
            float2 p = spos[i];
            float dx = p.x - xj, dy = p.y - yj;
            float r2 = fmaf(dx, dx, dy * dy);
            float nd = fmaf(dx, cj, dy * sj);
            float m  = fminf(nd, fmaf(-C20SQ, r2, nd * nd));
            float e  = (m > 0.0f) ? nd : INF;
            bool  c  = e < best;
            best = c ? e : best;  bidx = c ? i : bidx;
        }
        #pragma unroll
        for (int m = 1; m <= 16; m <<= 1) {
            float ob = __shfl_xor_sync(0xFFFFFFFFu, best, m);
            int   oi = __shfl_xor_sync(0xFFFFFFFFu, bidx, m);
            if (ob < best || (ob == best && oi < bidx)) { best = ob; bidx = oi; }
        }
    }

    if (lane == 0) {
        const float V0 = v0p[0], S0 = s0p[0], DTH = dthp[0];
        const float AMAX = amaxp[0], BB = bp[0];

        float4 ld = satt[bidx];                 // leader {cos, sin, v} (sorted idx)
        float dvx = ld.z * ld.x - vj * cj;
        float dvy = ld.z * ld.y - vj * sj;
        float ndv = fmaf(dvx, cj, dvy * sj);    // dv*cos(vdelpsi), exact incl. dv=0

        float sal   = best - lengths[jl];
        float sstar = S0 + vj * DTH + (vj * ndv) / (2.0f * sqrtf(AMAX * BB));
        float q  = vj / V0;
        float q2 = q * q;
        float afree = AMAX * (1.0f - q2 * q2);

        float action;
        if (stopi) {
            action = afree - AMAX;              // ratio = 1
        } else if (isinf(sal) || isnan(sal)) {
            action = afree;
        } else {
            float r = sstar / sal;
            action = afree - AMAX * r * r;
        }
        out[bat * NV + jl] = action;
    }
}

extern "C" void kernel_launch(void* const* d_in, const int* in_sizes, int n_in,
                              void* d_out, int out_size)
{
    const float* state   = (const float*)d_in[0];
    const float* lengths = (const float*)d_in[1];
    const float* v0      = (const float*)d_in[2];
    const float* s0      = (const float*)d_in[3];
    const float* dth     = (const float*)d_in[4];
    const float* amax    = (const float*)d_in[5];
    const float* b       = (const float*)d_in[6];
    float* out = (float*)d_out;

    prep_kernel<<<NB, 512>>>(state);
    dim3 grid(NV / WPB, NB);
    rulepolicy_kernel<<<grid, BTHREADS>>>(lengths, v0, s0, dth, amax, b, out);
}